// round 7
// baseline (speedup 1.0000x reference)
#include <cuda_runtime.h>
#include <cstdint>

// ---------------------------------------------------------------------------
// Q[n,m] = P[n] + R[m] + sum_h (w2[h]/2) * |a[n,h] + b[m,h]|
//   (relu(x) = (x+|x|)/2 ; rank-1 halves folded into per-row P/R)
// Inner loop: packed f32x2 add + fma, |.| folded as FFMA2 operand modifier.
// 64 threads/block, 64x64 tile, 8n x 8m per thread: 128 consecutive FFMA2
// per h2 between LDS batches -> dependency walls self-covered.
// ---------------------------------------------------------------------------

#define NMAX 2048
#define HID  64
#define HP   32   // h pairs

__device__ unsigned long long g_aT[HP][NMAX];  // pack(a[n][2h2], a[n][2h2+1])
__device__ unsigned long long g_bT[HP][NMAX];  // pack(b[m][2h2], b[m][2h2+1])
__device__ float g_P[NMAX];
__device__ float g_R[NMAX];

__device__ __forceinline__ unsigned long long pack2(float lo, float hi) {
    return (unsigned long long)__float_as_uint(lo) |
           ((unsigned long long)__float_as_uint(hi) << 32);
}

// ---------------------------------------------------------------------------
// Precompute: one warp per row; lane = h-pair. Warp-shuffle rank-1 reduce.
// ---------------------------------------------------------------------------
__global__ void __launch_bounds__(256) precompute_kernel(
    const float* __restrict__ job, const float* __restrict__ mac,
    const float* __restrict__ gvec,
    const float* __restrict__ Wj, const float* __restrict__ bj,
    const float* __restrict__ Wm, const float* __restrict__ bm,
    const float* __restrict__ Wg, const float* __restrict__ bg,
    const float* __restrict__ W1, const float* __restrict__ b1,
    const float* __restrict__ W2, const float* __restrict__ b2,
    int n, int m)
{
    const int row  = blockIdx.x * 8 + (threadIdx.x >> 5);
    const int lane = threadIdx.x & 31;
    if (row >= n + m) return;

    float2 w2p = *(const float2*)&W2[2 * lane];

    if (row < n) {
        const float x = job[row];
        float h0 = 0.0f, h1 = 0.0f;
        #pragma unroll
        for (int j = 0; j < 16; ++j) {
            float f = fmaxf(fmaf(x, Wj[j], bj[j]), 0.0f);
            float2 w = *(const float2*)&W1[j * HID + 2 * lane];
            h0 = fmaf(f, w.x, h0);
            h1 = fmaf(f, w.y, h1);
        }
        g_aT[lane][row] = pack2(h0, h1);
        float s = h0 * w2p.x + h1 * w2p.y;
        #pragma unroll
        for (int d = 16; d > 0; d >>= 1)
            s += __shfl_xor_sync(0xFFFFFFFFu, s, d);
        if (lane == 0) g_P[row] = 0.5f * s + b2[0];
    } else {
        const int mm = row - n;
        const float x = mac[mm];
        float2 bb = *(const float2*)&b1[2 * lane];
        float h0 = bb.x, h1 = bb.y;
        #pragma unroll
        for (int k = 0; k < 8; ++k) {
            float gf = bg[k];
            #pragma unroll
            for (int i = 0; i < 8; ++i)
                gf = fmaf(gvec[i], Wg[i * 8 + k], gf);
            gf = fmaxf(gf, 0.0f);
            float2 w = *(const float2*)&W1[(32 + k) * HID + 2 * lane];
            h0 = fmaf(gf, w.x, h0);
            h1 = fmaf(gf, w.y, h1);
        }
        #pragma unroll
        for (int j = 0; j < 16; ++j) {
            float f = fmaxf(fmaf(x, Wm[j], bm[j]), 0.0f);
            float2 w = *(const float2*)&W1[(16 + j) * HID + 2 * lane];
            h0 = fmaf(f, w.x, h0);
            h1 = fmaf(f, w.y, h1);
        }
        g_bT[lane][mm] = pack2(h0, h1);
        float s = h0 * w2p.x + h1 * w2p.y;
        #pragma unroll
        for (int d = 16; d > 0; d >>= 1)
            s += __shfl_xor_sync(0xFFFFFFFFu, s, d);
        if (lane == 0) g_R[mm] = 0.5f * s;
    }
}

// ---------------------------------------------------------------------------
// Core step: acc(f32x2) += |a + b| * w   (w pre-scaled by 0.5)
// ---------------------------------------------------------------------------
__device__ __forceinline__ void step(unsigned long long& acc,
                                     unsigned long long a,
                                     unsigned long long b,
                                     unsigned long long w)
{
    asm("{\n\t"
        ".reg .b64 t;\n\t"
        ".reg .f32 lo, hi;\n\t"
        "add.rn.f32x2 t, %1, %2;\n\t"
        "mov.b64 {lo, hi}, t;\n\t"
        "abs.f32 lo, lo;\n\t"
        "abs.f32 hi, hi;\n\t"
        "mov.b64 t, {lo, hi};\n\t"
        "fma.rn.f32x2 %0, t, %3, %0;\n\t"
        "}"
        : "+l"(acc)
        : "l"(a), "l"(b), "l"(w));
}

// ---------------------------------------------------------------------------
// Main kernel: 64 threads, 64x64 tile, 8n x 8m per thread, 4 CTAs/SM.
// ---------------------------------------------------------------------------
__global__ void __launch_bounds__(64, 4) qmain_kernel(
    const float* __restrict__ W2,
    float* __restrict__ out, int N, int M)
{
    __shared__ unsigned long long sA[HP][64];   // 16 KB
    __shared__ unsigned long long sB[HP][64];   // 16 KB
    __shared__ unsigned long long sW[HP];       // 256 B (0.5*w2 pairs)
    __shared__ float sP[64];
    __shared__ float sR[64];

    const int tid = threadIdx.x;
    const int nBase = blockIdx.y * 64;
    const int mBase = blockIdx.x * 64;

    if (tid < HP) {
        float2 w = *(const float2*)&W2[2 * tid];
        sW[tid] = pack2(0.5f * w.x, 0.5f * w.y);
    }
    sP[tid] = g_P[nBase + tid];
    sR[tid] = g_R[mBase + tid];

    // Fill sA, sB: 2048 entries each / 64 threads = 32 each, coalesced.
    #pragma unroll
    for (int i = 0; i < 32; ++i) {
        int idx = tid + i * 64;
        int h2 = idx >> 6, l = idx & 63;
        sA[h2][l] = g_aT[h2][nBase + l];
        sB[h2][l] = g_bT[h2][mBase + l];
    }
    __syncthreads();

    const int tx = tid & 7;         // m: 8 cols x 8
    const int ty = tid >> 3;        // n: 8 rows x 8
    const int n0 = ty * 8;
    const int m0 = tx * 8;

    unsigned long long acc[8][8];
    #pragma unroll
    for (int i = 0; i < 8; ++i)
        #pragma unroll
        for (int j = 0; j < 8; ++j)
            acc[i][j] = 0ull;

    #pragma unroll 2
    for (int h2 = 0; h2 < HP; ++h2) {
        unsigned long long w = sW[h2];
        unsigned long long A[8], B[8];
        #pragma unroll
        for (int i = 0; i < 4; ++i) {
            ulonglong2 a = *(const ulonglong2*)&sA[h2][n0 + 2 * i];
            A[2 * i] = a.x; A[2 * i + 1] = a.y;
            ulonglong2 b = *(const ulonglong2*)&sB[h2][m0 + 2 * i];
            B[2 * i] = b.x; B[2 * i + 1] = b.y;
        }
        #pragma unroll
        for (int i = 0; i < 8; ++i)
            #pragma unroll
            for (int j = 0; j < 8; ++j)
                step(acc[i][j], A[i], B[j], w);
    }

    // Epilogue: r = acc.lo + acc.hi + P[n] + R[m]
    #pragma unroll
    for (int i = 0; i < 8; ++i) {
        const float pn = sP[n0 + i];
        float r[8];
        #pragma unroll
        for (int j = 0; j < 8; ++j) {
            unsigned long long u = acc[i][j];
            r[j] = (__uint_as_float((unsigned)u) +
                    __uint_as_float((unsigned)(u >> 32))) + (pn + sR[m0 + j]);
        }
        float* orow = &out[(size_t)(nBase + n0 + i) * M + (mBase + m0)];
        *(float4*)&orow[0] = make_float4(r[0], r[1], r[2], r[3]);
        *(float4*)&orow[4] = make_float4(r[4], r[5], r[6], r[7]);
    }
}

// ---------------------------------------------------------------------------
// Launch
// ---------------------------------------------------------------------------
extern "C" void kernel_launch(void* const* d_in, const int* in_sizes, int n_in,
                              void* d_out, int out_size)
{
    const float* job  = (const float*)d_in[0];
    const float* mac  = (const float*)d_in[1];
    const float* gvec = (const float*)d_in[2];
    const float* Wj   = (const float*)d_in[3];
    const float* bj   = (const float*)d_in[4];
    const float* Wm   = (const float*)d_in[5];
    const float* bm   = (const float*)d_in[6];
    const float* Wg   = (const float*)d_in[7];
    const float* bg   = (const float*)d_in[8];
    const float* W1   = (const float*)d_in[9];
    const float* b1   = (const float*)d_in[10];
    const float* W2   = (const float*)d_in[11];
    const float* b2   = (const float*)d_in[12];
    float* out = (float*)d_out;

    const int N = in_sizes[0];
    const int M = in_sizes[1];

    int rows = N + M;
    precompute_kernel<<<(rows + 7) / 8, 256>>>(
        job, mac, gvec, Wj, bj, Wm, bm, Wg, bg, W1, b1, W2, b2, N, M);

    dim3 grid(M / 64, N / 64);
    qmain_kernel<<<grid, 64>>>(W2, out, N, M);
}

// round 8
// speedup vs baseline: 1.0878x; 1.0878x over previous
#include <cuda_runtime.h>
#include <cstdint>

// ---------------------------------------------------------------------------
// Q[n,m] = P[n] + R[m] + sum_h (w2[h]/2)|a[n,h] + b[m,h]|
// Pre-scale rows by |w|/2:  (w/2)|a+b| = sign(w) * |a' + b'|.
// h-space is permuted on device: [pos pairs | mixed pair? | neg pairs],
// so the inner loop needs NO multiplier: t = add2(a',b'); acc += (+|t|/-|t|)
// -> both packed ops read only 2 register pairs (rt=2, no RF bank conflict).
// ---------------------------------------------------------------------------

#define NMAX 2048
#define HID  64
#define HP   32   // h pairs

__device__ unsigned long long g_aT[HP][NMAX];  // scaled, permuted job rows
__device__ unsigned long long g_bT[HP][NMAX];  // scaled, permuted machine rows
__device__ float g_P[NMAX];
__device__ float g_R[NMAX];
__device__ int g_slotH[HID];   // permuted h index per slot
__device__ int g_K1;           // # pure-positive pairs
__device__ int g_mix;          // 1 if a mixed (+,-) pair exists at slot K1

__device__ __forceinline__ unsigned long long pack2(float lo, float hi) {
    return (unsigned long long)__float_as_uint(lo) |
           ((unsigned long long)__float_as_uint(hi) << 32);
}

// ---------------------------------------------------------------------------
// Setup: build the sign-partitioned permutation of h (single tiny block).
// ---------------------------------------------------------------------------
__global__ void setup_kernel(const float* __restrict__ W2) {
    __shared__ int posList[HID], negList[HID];
    __shared__ int cnt[2];
    int t = threadIdx.x;
    if (t < 2) cnt[t] = 0;
    __syncthreads();
    if (t < HID) {
        float w = W2[t];
        if (w >= 0.0f) { int i = atomicAdd(&cnt[0], 1); posList[i] = t; }
        else           { int i = atomicAdd(&cnt[1], 1); negList[i] = t; }
    }
    __syncthreads();
    if (t == 0) {
        int pc = cnt[0], nc = cnt[1];
        int p2  = pc & ~1;      // even # of positives in pure pairs
        int mix = pc & 1;       // both pc,nc odd together (pc+nc=64)
        int s = 0;
        for (int i = 0; i < p2; ++i) g_slotH[s++] = posList[i];
        if (mix) { g_slotH[s++] = posList[p2]; g_slotH[s++] = negList[0]; }
        for (int i = mix; i < nc; ++i) g_slotH[s++] = negList[i];
        g_K1  = p2 >> 1;
        g_mix = mix;
    }
}

// ---------------------------------------------------------------------------
// Precompute: one warp per row; lane = slot pair. Produces scaled+permuted
// packed rows and the rank-1 terms P/R (with original signed w/2).
// ---------------------------------------------------------------------------
__global__ void __launch_bounds__(256) precompute_kernel(
    const float* __restrict__ job, const float* __restrict__ mac,
    const float* __restrict__ gvec,
    const float* __restrict__ Wj, const float* __restrict__ bj,
    const float* __restrict__ Wm, const float* __restrict__ bm,
    const float* __restrict__ Wg, const float* __restrict__ bg,
    const float* __restrict__ W1, const float* __restrict__ b1,
    const float* __restrict__ W2, const float* __restrict__ b2,
    int n, int m)
{
    const int row  = blockIdx.x * 8 + (threadIdx.x >> 5);
    const int lane = threadIdx.x & 31;
    if (row >= n + m) return;

    const int h0 = g_slotH[2 * lane];
    const int h1 = g_slotH[2 * lane + 1];
    const float w0 = W2[h0], w1 = W2[h1];
    const float sc0 = 0.5f * fabsf(w0), sc1 = 0.5f * fabsf(w1);

    if (row < n) {
        const float x = job[row];
        float f0 = 0.0f, f1 = 0.0f;
        #pragma unroll
        for (int j = 0; j < 16; ++j) {
            float f = fmaxf(fmaf(x, Wj[j], bj[j]), 0.0f);
            f0 = fmaf(f, W1[j * HID + h0], f0);
            f1 = fmaf(f, W1[j * HID + h1], f1);
        }
        g_aT[lane][row] = pack2(f0 * sc0, f1 * sc1);
        float s = f0 * (0.5f * w0) + f1 * (0.5f * w1);
        #pragma unroll
        for (int d = 16; d > 0; d >>= 1)
            s += __shfl_xor_sync(0xFFFFFFFFu, s, d);
        if (lane == 0) g_P[row] = s + b2[0];
    } else {
        const int mm = row - n;
        const float x = mac[mm];
        float f0 = b1[h0], f1 = b1[h1];
        #pragma unroll
        for (int k = 0; k < 8; ++k) {
            float gf = bg[k];
            #pragma unroll
            for (int i = 0; i < 8; ++i)
                gf = fmaf(gvec[i], Wg[i * 8 + k], gf);
            gf = fmaxf(gf, 0.0f);
            f0 = fmaf(gf, W1[(32 + k) * HID + h0], f0);
            f1 = fmaf(gf, W1[(32 + k) * HID + h1], f1);
        }
        #pragma unroll
        for (int j = 0; j < 16; ++j) {
            float f = fmaxf(fmaf(x, Wm[j], bm[j]), 0.0f);
            f0 = fmaf(f, W1[(16 + j) * HID + h0], f0);
            f1 = fmaf(f, W1[(16 + j) * HID + h1], f1);
        }
        g_bT[lane][mm] = pack2(f0 * sc0, f1 * sc1);
        float s = f0 * (0.5f * w0) + f1 * (0.5f * w1);
        #pragma unroll
        for (int d = 16; d > 0; d >>= 1)
            s += __shfl_xor_sync(0xFFFFFFFFu, s, d);
        if (lane == 0) g_R[mm] = s;
    }
}

// ---------------------------------------------------------------------------
// Steps. abs/neg expected to fold into the FADD2 source operand modifier.
// ---------------------------------------------------------------------------
__device__ __forceinline__ void stepP(unsigned long long& acc,
                                      unsigned long long a,
                                      unsigned long long b)
{
    asm("{\n\t"
        ".reg .b64 t;\n\t"
        ".reg .f32 lo, hi;\n\t"
        "add.rn.f32x2 t, %1, %2;\n\t"
        "mov.b64 {lo, hi}, t;\n\t"
        "abs.f32 lo, lo;\n\t"
        "abs.f32 hi, hi;\n\t"
        "mov.b64 t, {lo, hi};\n\t"
        "add.rn.f32x2 %0, %0, t;\n\t"
        "}"
        : "+l"(acc) : "l"(a), "l"(b));
}

__device__ __forceinline__ void stepN(unsigned long long& acc,
                                      unsigned long long a,
                                      unsigned long long b)
{
    asm("{\n\t"
        ".reg .b64 t;\n\t"
        ".reg .f32 lo, hi;\n\t"
        "add.rn.f32x2 t, %1, %2;\n\t"
        "mov.b64 {lo, hi}, t;\n\t"
        "abs.f32 lo, lo;\n\t"
        "abs.f32 hi, hi;\n\t"
        "neg.f32 lo, lo;\n\t"
        "neg.f32 hi, hi;\n\t"
        "mov.b64 t, {lo, hi};\n\t"
        "add.rn.f32x2 %0, %0, t;\n\t"
        "}"
        : "+l"(acc) : "l"(a), "l"(b));
}

__device__ __forceinline__ void stepM(unsigned long long& acc,
                                      unsigned long long a,
                                      unsigned long long b,
                                      unsigned long long sv)
{
    asm("{\n\t"
        ".reg .b64 t;\n\t"
        ".reg .f32 lo, hi;\n\t"
        "add.rn.f32x2 t, %1, %2;\n\t"
        "mov.b64 {lo, hi}, t;\n\t"
        "abs.f32 lo, lo;\n\t"
        "abs.f32 hi, hi;\n\t"
        "mov.b64 t, {lo, hi};\n\t"
        "fma.rn.f32x2 %0, t, %3, %0;\n\t"
        "}"
        : "+l"(acc) : "l"(a), "l"(b), "l"(sv));
}

// ---------------------------------------------------------------------------
// Main kernel: 128 threads, 64x64 tile, 8n x 4m per thread, 4 CTAs/SM.
// Segmented h2 loop: [0,K1) += |t| ; mixed (+,-) ; [K2,32) -= |t|.
// ---------------------------------------------------------------------------
__global__ void __launch_bounds__(128, 4) qmain_kernel(
    float* __restrict__ out, int N, int M)
{
    __shared__ unsigned long long sA[HP][64];   // 16 KB
    __shared__ unsigned long long sB[HP][64];   // 16 KB
    __shared__ float sP[64];
    __shared__ float sR[64];

    const int tid = threadIdx.x;
    const int nBase = blockIdx.y * 64;
    const int mBase = blockIdx.x * 64;

    const int K1  = g_K1;
    const int mix = g_mix;

    if (tid < 64) sP[tid] = g_P[nBase + tid];
    else          sR[tid - 64] = g_R[mBase + (tid - 64)];

    #pragma unroll
    for (int i = 0; i < 16; ++i) {
        int idx = tid + i * 128;
        int h2 = idx >> 6, l = idx & 63;
        sA[h2][l] = g_aT[h2][nBase + l];
        sB[h2][l] = g_bT[h2][mBase + l];
    }
    __syncthreads();

    const int tx = tid & 15;        // m: 16 cols x 4
    const int ty = tid >> 4;        // n: 8 rows x 8
    const int n0 = ty * 8;
    const int m0 = tx * 4;

    unsigned long long acc[8][4];
    #pragma unroll
    for (int i = 0; i < 8; ++i)
        #pragma unroll
        for (int j = 0; j < 4; ++j)
            acc[i][j] = 0ull;

    unsigned long long A[8], B[4];

    int h2 = 0;
    #pragma unroll 4
    for (; h2 < K1; ++h2) {
        #pragma unroll
        for (int i = 0; i < 4; ++i) {
            ulonglong2 a = *(const ulonglong2*)&sA[h2][n0 + 2 * i];
            A[2 * i] = a.x; A[2 * i + 1] = a.y;
        }
        #pragma unroll
        for (int j = 0; j < 2; ++j) {
            ulonglong2 b = *(const ulonglong2*)&sB[h2][m0 + 2 * j];
            B[2 * j] = b.x; B[2 * j + 1] = b.y;
        }
        #pragma unroll
        for (int i = 0; i < 8; ++i)
            #pragma unroll
            for (int j = 0; j < 4; ++j)
                stepP(acc[i][j], A[i], B[j]);
    }

    if (mix) {
        const unsigned long long sv = pack2(1.0f, -1.0f);
        #pragma unroll
        for (int i = 0; i < 4; ++i) {
            ulonglong2 a = *(const ulonglong2*)&sA[h2][n0 + 2 * i];
            A[2 * i] = a.x; A[2 * i + 1] = a.y;
        }
        #pragma unroll
        for (int j = 0; j < 2; ++j) {
            ulonglong2 b = *(const ulonglong2*)&sB[h2][m0 + 2 * j];
            B[2 * j] = b.x; B[2 * j + 1] = b.y;
        }
        #pragma unroll
        for (int i = 0; i < 8; ++i)
            #pragma unroll
            for (int j = 0; j < 4; ++j)
                stepM(acc[i][j], A[i], B[j], sv);
        ++h2;
    }

    #pragma unroll 4
    for (; h2 < HP; ++h2) {
        #pragma unroll
        for (int i = 0; i < 4; ++i) {
            ulonglong2 a = *(const ulonglong2*)&sA[h2][n0 + 2 * i];
            A[2 * i] = a.x; A[2 * i + 1] = a.y;
        }
        #pragma unroll
        for (int j = 0; j < 2; ++j) {
            ulonglong2 b = *(const ulonglong2*)&sB[h2][m0 + 2 * j];
            B[2 * j] = b.x; B[2 * j + 1] = b.y;
        }
        #pragma unroll
        for (int i = 0; i < 8; ++i)
            #pragma unroll
            for (int j = 0; j < 4; ++j)
                stepN(acc[i][j], A[i], B[j]);
    }

    // Epilogue: r = acc.lo + acc.hi + P[n] + R[m]
    #pragma unroll
    for (int i = 0; i < 8; ++i) {
        const float pn = sP[n0 + i];
        float r[4];
        #pragma unroll
        for (int j = 0; j < 4; ++j) {
            unsigned long long u = acc[i][j];
            r[j] = (__uint_as_float((unsigned)u) +
                    __uint_as_float((unsigned)(u >> 32))) + (pn + sR[m0 + j]);
        }
        float4 v = make_float4(r[0], r[1], r[2], r[3]);
        *(float4*)&out[(size_t)(nBase + n0 + i) * M + (mBase + m0)] = v;
    }
}

// ---------------------------------------------------------------------------
// Launch
// ---------------------------------------------------------------------------
extern "C" void kernel_launch(void* const* d_in, const int* in_sizes, int n_in,
                              void* d_out, int out_size)
{
    const float* job  = (const float*)d_in[0];
    const float* mac  = (const float*)d_in[1];
    const float* gvec = (const float*)d_in[2];
    const float* Wj   = (const float*)d_in[3];
    const float* bj   = (const float*)d_in[4];
    const float* Wm   = (const float*)d_in[5];
    const float* bm   = (const float*)d_in[6];
    const float* Wg   = (const float*)d_in[7];
    const float* bg   = (const float*)d_in[8];
    const float* W1   = (const float*)d_in[9];
    const float* b1   = (const float*)d_in[10];
    const float* W2   = (const float*)d_in[11];
    const float* b2   = (const float*)d_in[12];
    float* out = (float*)d_out;

    const int N = in_sizes[0];
    const int M = in_sizes[1];

    setup_kernel<<<1, 64>>>(W2);

    int rows = N + M;
    precompute_kernel<<<(rows + 7) / 8, 256>>>(
        job, mac, gvec, Wj, bj, Wm, bm, Wg, bg, W1, b1, W2, b2, N, M);

    dim3 grid(M / 64, N / 64);
    qmain_kernel<<<grid, 128>>>(out, N, M);
}

// round 10
// speedup vs baseline: 1.0910x; 1.0030x over previous
#include <cuda_runtime.h>
#include <cstdint>

// ---------------------------------------------------------------------------
// Q[n,m] = P[n] + R[m] + sum_h (w2[h]/2)|a[n,h] + b[m,h]|
// Rows pre-scaled by |w|/2:  (w/2)|a+b| = sign(w) * |a' + b'|.
// h-space permuted (computed in-warp, no setup kernel): positives first,
// then negatives; if #pos is odd the boundary pair is mixed (+,-).
// Inner loop: add2 + add2 with |.| folded as operand modifier -> both packed
// ops read only 2 register pairs (rt=2, no RF bank conflict).
// ---------------------------------------------------------------------------

#define NMAX 2048
#define HID  64
#define HP   32   // h pairs

__device__ unsigned long long g_aT[HP][NMAX];  // scaled, permuted job rows
__device__ unsigned long long g_bT[HP][NMAX];  // scaled, permuted machine rows
__device__ float g_P[NMAX];
__device__ float g_R[NMAX];
__device__ int g_K1;           // # pure-positive pairs
__device__ int g_mix;          // 1 if a mixed (+,-) pair exists at slot K1

__device__ __forceinline__ unsigned long long pack2(float lo, float hi) {
    return (unsigned long long)__float_as_uint(lo) |
           ((unsigned long long)__float_as_uint(hi) << 32);
}

// slot -> h under the sign partition, from two 32-bit sign ballots.
__device__ __forceinline__ int slot_to_h(int s, unsigned bal0, unsigned bal1,
                                         int pc) {
    if (s < pc) {
        int c0 = __popc(bal0);
        return (s < c0) ? (int)__fns(bal0, 0, s + 1)
                        : 32 + (int)__fns(bal1, 0, s - c0 + 1);
    } else {
        int k = s - pc;
        unsigned nb0 = ~bal0, nb1 = ~bal1;
        int c0 = __popc(nb0);
        return (k < c0) ? (int)__fns(nb0, 0, k + 1)
                        : 32 + (int)__fns(nb1, 0, k - c0 + 1);
    }
}

// ---------------------------------------------------------------------------
// Precompute: one warp per row; lane = slot pair. Produces scaled+permuted
// packed rows and the rank-1 terms P/R. Permutation derived per-warp.
// ---------------------------------------------------------------------------
__global__ void __launch_bounds__(256) precompute_kernel(
    const float* __restrict__ job, const float* __restrict__ mac,
    const float* __restrict__ gvec,
    const float* __restrict__ Wj, const float* __restrict__ bj,
    const float* __restrict__ Wm, const float* __restrict__ bm,
    const float* __restrict__ Wg, const float* __restrict__ bg,
    const float* __restrict__ W1, const float* __restrict__ b1,
    const float* __restrict__ W2, const float* __restrict__ b2,
    int n, int m)
{
    const int row  = blockIdx.x * 8 + (threadIdx.x >> 5);
    const int lane = threadIdx.x & 31;
    if (row >= n + m) return;

    // Sign partition of h-space (identical in every warp, deterministic).
    const float w_lo = W2[lane];
    const float w_hi = W2[lane + 32];
    const unsigned bal0 = __ballot_sync(0xFFFFFFFFu, w_lo >= 0.0f);
    const unsigned bal1 = __ballot_sync(0xFFFFFFFFu, w_hi >= 0.0f);
    const int pc = __popc(bal0) + __popc(bal1);

    if (blockIdx.x == 0 && threadIdx.x == 0) {
        g_K1  = pc >> 1;
        g_mix = pc & 1;
    }

    const int h0 = slot_to_h(2 * lane,     bal0, bal1, pc);
    const int h1 = slot_to_h(2 * lane + 1, bal0, bal1, pc);
    // Direct global reads (a lane-varying ternary inside __shfl_sync picks
    // the SOURCE lane's selection, not ours -> must not use shuffle here).
    const float w0 = W2[h0];
    const float w1 = W2[h1];
    const float sc0 = 0.5f * fabsf(w0), sc1 = 0.5f * fabsf(w1);

    if (row < n) {
        const float x = job[row];
        float f0 = 0.0f, f1 = 0.0f;
        #pragma unroll
        for (int j = 0; j < 16; ++j) {
            float f = fmaxf(fmaf(x, Wj[j], bj[j]), 0.0f);
            f0 = fmaf(f, W1[j * HID + h0], f0);
            f1 = fmaf(f, W1[j * HID + h1], f1);
        }
        g_aT[lane][row] = pack2(f0 * sc0, f1 * sc1);
        float s = f0 * (0.5f * w0) + f1 * (0.5f * w1);
        #pragma unroll
        for (int d = 16; d > 0; d >>= 1)
            s += __shfl_xor_sync(0xFFFFFFFFu, s, d);
        if (lane == 0) g_P[row] = s + b2[0];
    } else {
        const int mm = row - n;
        const float x = mac[mm];
        float f0 = b1[h0], f1 = b1[h1];
        #pragma unroll
        for (int k = 0; k < 8; ++k) {
            float gf = bg[k];
            #pragma unroll
            for (int i = 0; i < 8; ++i)
                gf = fmaf(gvec[i], Wg[i * 8 + k], gf);
            gf = fmaxf(gf, 0.0f);
            f0 = fmaf(gf, W1[(32 + k) * HID + h0], f0);
            f1 = fmaf(gf, W1[(32 + k) * HID + h1], f1);
        }
        #pragma unroll
        for (int j = 0; j < 16; ++j) {
            float f = fmaxf(fmaf(x, Wm[j], bm[j]), 0.0f);
            f0 = fmaf(f, W1[(16 + j) * HID + h0], f0);
            f1 = fmaf(f, W1[(16 + j) * HID + h1], f1);
        }
        g_bT[lane][mm] = pack2(f0 * sc0, f1 * sc1);
        float s = f0 * (0.5f * w0) + f1 * (0.5f * w1);
        #pragma unroll
        for (int d = 16; d > 0; d >>= 1)
            s += __shfl_xor_sync(0xFFFFFFFFu, s, d);
        if (lane == 0) g_R[mm] = s;
    }
}

// ---------------------------------------------------------------------------
// Steps. abs/neg fold into the FADD2 source operand modifier.
// ---------------------------------------------------------------------------
__device__ __forceinline__ void stepP(unsigned long long& acc,
                                      unsigned long long a,
                                      unsigned long long b)
{
    asm("{\n\t"
        ".reg .b64 t;\n\t"
        ".reg .f32 lo, hi;\n\t"
        "add.rn.f32x2 t, %1, %2;\n\t"
        "mov.b64 {lo, hi}, t;\n\t"
        "abs.f32 lo, lo;\n\t"
        "abs.f32 hi, hi;\n\t"
        "mov.b64 t, {lo, hi};\n\t"
        "add.rn.f32x2 %0, %0, t;\n\t"
        "}"
        : "+l"(acc) : "l"(a), "l"(b));
}

__device__ __forceinline__ void stepN(unsigned long long& acc,
                                      unsigned long long a,
                                      unsigned long long b)
{
    asm("{\n\t"
        ".reg .b64 t;\n\t"
        ".reg .f32 lo, hi;\n\t"
        "add.rn.f32x2 t, %1, %2;\n\t"
        "mov.b64 {lo, hi}, t;\n\t"
        "abs.f32 lo, lo;\n\t"
        "abs.f32 hi, hi;\n\t"
        "neg.f32 lo, lo;\n\t"
        "neg.f32 hi, hi;\n\t"
        "mov.b64 t, {lo, hi};\n\t"
        "add.rn.f32x2 %0, %0, t;\n\t"
        "}"
        : "+l"(acc) : "l"(a), "l"(b));
}

__device__ __forceinline__ void stepM(unsigned long long& acc,
                                      unsigned long long a,
                                      unsigned long long b,
                                      unsigned long long sv)
{
    asm("{\n\t"
        ".reg .b64 t;\n\t"
        ".reg .f32 lo, hi;\n\t"
        "add.rn.f32x2 t, %1, %2;\n\t"
        "mov.b64 {lo, hi}, t;\n\t"
        "abs.f32 lo, lo;\n\t"
        "abs.f32 hi, hi;\n\t"
        "mov.b64 t, {lo, hi};\n\t"
        "fma.rn.f32x2 %0, t, %3, %0;\n\t"
        "}"
        : "+l"(acc) : "l"(a), "l"(b), "l"(sv));
}

// ---------------------------------------------------------------------------
// Main kernel: 128 threads, 64x64 tile, 8n x 4m per thread, 4 CTAs/SM.
// Segmented h2 loop: [0,K1) += |t| ; mixed (+,-) ; rest -= |t|.
// ---------------------------------------------------------------------------
__global__ void __launch_bounds__(128, 4) qmain_kernel(
    float* __restrict__ out, int N, int M)
{
    __shared__ unsigned long long sA[HP][64];   // 16 KB
    __shared__ unsigned long long sB[HP][64];   // 16 KB
    __shared__ float sP[64];
    __shared__ float sR[64];

    const int tid = threadIdx.x;
    const int nBase = blockIdx.y * 64;
    const int mBase = blockIdx.x * 64;

    const int K1  = g_K1;
    const int mix = g_mix;

    if (tid < 64) sP[tid] = g_P[nBase + tid];
    else          sR[tid - 64] = g_R[mBase + (tid - 64)];

    #pragma unroll
    for (int i = 0; i < 16; ++i) {
        int idx = tid + i * 128;
        int h2 = idx >> 6, l = idx & 63;
        sA[h2][l] = g_aT[h2][nBase + l];
        sB[h2][l] = g_bT[h2][mBase + l];
    }
    __syncthreads();

    const int tx = tid & 15;        // m: 16 cols x 4
    const int ty = tid >> 4;        // n: 8 rows x 8
    const int n0 = ty * 8;
    const int m0 = tx * 4;

    unsigned long long acc[8][4];
    #pragma unroll
    for (int i = 0; i < 8; ++i)
        #pragma unroll
        for (int j = 0; j < 4; ++j)
            acc[i][j] = 0ull;

    unsigned long long A[8], B[4];

    int h2 = 0;
    #pragma unroll 4
    for (; h2 < K1; ++h2) {
        #pragma unroll
        for (int i = 0; i < 4; ++i) {
            ulonglong2 a = *(const ulonglong2*)&sA[h2][n0 + 2 * i];
            A[2 * i] = a.x; A[2 * i + 1] = a.y;
        }
        #pragma unroll
        for (int j = 0; j < 2; ++j) {
            ulonglong2 b = *(const ulonglong2*)&sB[h2][m0 + 2 * j];
            B[2 * j] = b.x; B[2 * j + 1] = b.y;
        }
        #pragma unroll
        for (int i = 0; i < 8; ++i)
            #pragma unroll
            for (int j = 0; j < 4; ++j)
                stepP(acc[i][j], A[i], B[j]);
    }

    if (mix) {
        const unsigned long long sv = pack2(1.0f, -1.0f);
        #pragma unroll
        for (int i = 0; i < 4; ++i) {
            ulonglong2 a = *(const ulonglong2*)&sA[h2][n0 + 2 * i];
            A[2 * i] = a.x; A[2 * i + 1] = a.y;
        }
        #pragma unroll
        for (int j = 0; j < 2; ++j) {
            ulonglong2 b = *(const ulonglong2*)&sB[h2][m0 + 2 * j];
            B[2 * j] = b.x; B[2 * j + 1] = b.y;
        }
        #pragma unroll
        for (int i = 0; i < 8; ++i)
            #pragma unroll
            for (int j = 0; j < 4; ++j)
                stepM(acc[i][j], A[i], B[j], sv);
        ++h2;
    }

    #pragma unroll 4
    for (; h2 < HP; ++h2) {
        #pragma unroll
        for (int i = 0; i < 4; ++i) {
            ulonglong2 a = *(const ulonglong2*)&sA[h2][n0 + 2 * i];
            A[2 * i] = a.x; A[2 * i + 1] = a.y;
        }
        #pragma unroll
        for (int j = 0; j < 2; ++j) {
            ulonglong2 b = *(const ulonglong2*)&sB[h2][m0 + 2 * j];
            B[2 * j] = b.x; B[2 * j + 1] = b.y;
        }
        #pragma unroll
        for (int i = 0; i < 8; ++i)
            #pragma unroll
            for (int j = 0; j < 4; ++j)
                stepN(acc[i][j], A[i], B[j]);
    }

    // Epilogue: r = acc.lo + acc.hi + P[n] + R[m]
    #pragma unroll
    for (int i = 0; i < 8; ++i) {
        const float pn = sP[n0 + i];
        float r[4];
        #pragma unroll
        for (int j = 0; j < 4; ++j) {
            unsigned long long u = acc[i][j];
            r[j] = (__uint_as_float((unsigned)u) +
                    __uint_as_float((unsigned)(u >> 32))) + (pn + sR[m0 + j]);
        }
        float4 v = make_float4(r[0], r[1], r[2], r[3]);
        *(float4*)&out[(size_t)(nBase + n0 + i) * M + (mBase + m0)] = v;
    }
}

// ---------------------------------------------------------------------------
// Launch
// ---------------------------------------------------------------------------
extern "C" void kernel_launch(void* const* d_in, const int* in_sizes, int n_in,
                              void* d_out, int out_size)
{
    const float* job  = (const float*)d_in[0];
    const float* mac  = (const float*)d_in[1];
    const float* gvec = (const float*)d_in[2];
    const float* Wj   = (const float*)d_in[3];
    const float* bj   = (const float*)d_in[4];
    const float* Wm   = (const float*)d_in[5];
    const float* bm   = (const float*)d_in[6];
    const float* Wg   = (const float*)d_in[7];
    const float* bg   = (const float*)d_in[8];
    const float* W1   = (const float*)d_in[9];
    const float* b1   = (const float*)d_in[10];
    const float* W2   = (const float*)d_in[11];
    const float* b2   = (const float*)d_in[12];
    float* out = (float*)d_out;

    const int N = in_sizes[0];
    const int M = in_sizes[1];

    int rows = N + M;
    precompute_kernel<<<(rows + 7) / 8, 256>>>(
        job, mac, gvec, Wj, bj, Wm, bm, Wg, bg, W1, b1, W2, b2, N, M);

    dim3 grid(M / 64, N / 64);
    qmain_kernel<<<grid, 128>>>(out, N, M);
}

// round 11
// speedup vs baseline: 1.1313x; 1.0369x over previous
#include <cuda_runtime.h>
#include <cstdint>

// ---------------------------------------------------------------------------
// Q[n,m] = P[n] + R[m] + sum_h (w2[h]/2)|a[n,h] + b[m,h]|
// Rows pre-scaled by |w|/2:  (w/2)|a+b| = sign(w) * |a' + b'|.
// h-space permuted: positives first, then negatives (mixed pair if #pos odd).
// Precompute: features computed in ORIGINAL h order (coalesced W1 loads),
// permutation applied afterwards via warp shuffles + local select.
// Inner loop: add2 + add2 with |.|/-|.| folded as operand modifiers.
// ---------------------------------------------------------------------------

#define NMAX 2048
#define HID  64
#define HP   32   // h pairs

__device__ unsigned long long g_aT[HP][NMAX];  // scaled, permuted job rows
__device__ unsigned long long g_bT[HP][NMAX];  // scaled, permuted machine rows
__device__ float g_P[NMAX];
__device__ float g_R[NMAX];
__device__ int g_K1;           // # pure-positive pairs
__device__ int g_mix;          // 1 if a mixed (+,-) pair exists at slot K1

__device__ __forceinline__ unsigned long long pack2(float lo, float hi) {
    return (unsigned long long)__float_as_uint(lo) |
           ((unsigned long long)__float_as_uint(hi) << 32);
}

// slot -> h under the sign partition, from two 32-bit sign ballots.
__device__ __forceinline__ int slot_to_h(int s, unsigned bal0, unsigned bal1,
                                         int pc) {
    if (s < pc) {
        int c0 = __popc(bal0);
        return (s < c0) ? (int)__fns(bal0, 0, s + 1)
                        : 32 + (int)__fns(bal1, 0, s - c0 + 1);
    } else {
        int k = s - pc;
        unsigned nb0 = ~bal0, nb1 = ~bal1;
        int c0 = __popc(nb0);
        return (k < c0) ? (int)__fns(nb0, 0, k + 1)
                        : 32 + (int)__fns(nb1, 0, k - c0 + 1);
    }
}

// Fetch original-order value for h index: source lane h>>1 holds (f0,f1);
// shuffle BOTH components, select locally (selection must not ride inside
// the shuffle's value expression).
__device__ __forceinline__ float perm_fetch(float f0, float f1, int h) {
    float va = __shfl_sync(0xFFFFFFFFu, f0, h >> 1);
    float vb = __shfl_sync(0xFFFFFFFFu, f1, h >> 1);
    return (h & 1) ? vb : va;
}

// ---------------------------------------------------------------------------
// Precompute: one warp per row; lane = h-pair (original order), then permute.
// ---------------------------------------------------------------------------
__global__ void __launch_bounds__(256) precompute_kernel(
    const float* __restrict__ job, const float* __restrict__ mac,
    const float* __restrict__ gvec,
    const float* __restrict__ Wj, const float* __restrict__ bj,
    const float* __restrict__ Wm, const float* __restrict__ bm,
    const float* __restrict__ Wg, const float* __restrict__ bg,
    const float* __restrict__ W1, const float* __restrict__ b1,
    const float* __restrict__ W2, const float* __restrict__ b2,
    int n, int m)
{
    const int row  = blockIdx.x * 8 + (threadIdx.x >> 5);
    const int lane = threadIdx.x & 31;
    if (row >= n + m) return;

    // Sign partition of h-space (identical in every warp, deterministic).
    const float w_lo = W2[lane];
    const float w_hi = W2[lane + 32];
    const unsigned bal0 = __ballot_sync(0xFFFFFFFFu, w_lo >= 0.0f);
    const unsigned bal1 = __ballot_sync(0xFFFFFFFFu, w_hi >= 0.0f);
    const int pc = __popc(bal0) + __popc(bal1);

    if (blockIdx.x == 0 && threadIdx.x == 0) {
        g_K1  = pc >> 1;
        g_mix = pc & 1;
    }

    const int h0 = slot_to_h(2 * lane,     bal0, bal1, pc);
    const int h1 = slot_to_h(2 * lane + 1, bal0, bal1, pc);

    const float2 w2p = *(const float2*)&W2[2 * lane];  // original order

    float f0, f1;   // features for ORIGINAL h = 2*lane, 2*lane+1
    if (row < n) {
        const float x = job[row];
        f0 = 0.0f; f1 = 0.0f;
        #pragma unroll
        for (int j = 0; j < 16; ++j) {
            float f = fmaxf(fmaf(x, Wj[j], bj[j]), 0.0f);
            float2 w = *(const float2*)&W1[j * HID + 2 * lane];
            f0 = fmaf(f, w.x, f0);
            f1 = fmaf(f, w.y, f1);
        }
    } else {
        const int mm = row - n;
        const float x = mac[mm];
        float2 bb = *(const float2*)&b1[2 * lane];
        f0 = bb.x; f1 = bb.y;
        #pragma unroll
        for (int k = 0; k < 8; ++k) {
            float gf = bg[k];
            #pragma unroll
            for (int i = 0; i < 8; ++i)
                gf = fmaf(gvec[i], Wg[i * 8 + k], gf);
            gf = fmaxf(gf, 0.0f);
            float2 w = *(const float2*)&W1[(32 + k) * HID + 2 * lane];
            f0 = fmaf(gf, w.x, f0);
            f1 = fmaf(gf, w.y, f1);
        }
        #pragma unroll
        for (int j = 0; j < 16; ++j) {
            float f = fmaxf(fmaf(x, Wm[j], bm[j]), 0.0f);
            float2 w = *(const float2*)&W1[(16 + j) * HID + 2 * lane];
            f0 = fmaf(f, w.x, f0);
            f1 = fmaf(f, w.y, f1);
        }
    }

    // Rank-1 term (permutation-invariant, original order).
    float s = f0 * (0.5f * w2p.x) + f1 * (0.5f * w2p.y);
    #pragma unroll
    for (int d = 16; d > 0; d >>= 1)
        s += __shfl_xor_sync(0xFFFFFFFFu, s, d);

    // Apply permutation via register shuffles, then scale by |w|/2.
    const float v0 = perm_fetch(f0, f1, h0);
    const float v1 = perm_fetch(f0, f1, h1);
    const float w0 = perm_fetch(w2p.x, w2p.y, h0);
    const float w1 = perm_fetch(w2p.x, w2p.y, h1);
    const unsigned long long packed =
        pack2(v0 * (0.5f * fabsf(w0)), v1 * (0.5f * fabsf(w1)));

    if (row < n) {
        g_aT[lane][row] = packed;
        if (lane == 0) g_P[row] = s + b2[0];
    } else {
        g_bT[lane][row - n] = packed;
        if (lane == 0) g_R[row - n] = s;
    }
}

// ---------------------------------------------------------------------------
// Steps. abs/neg fold into the FADD2 source operand modifier.
// ---------------------------------------------------------------------------
__device__ __forceinline__ void stepP(unsigned long long& acc,
                                      unsigned long long a,
                                      unsigned long long b)
{
    asm("{\n\t"
        ".reg .b64 t;\n\t"
        ".reg .f32 lo, hi;\n\t"
        "add.rn.f32x2 t, %1, %2;\n\t"
        "mov.b64 {lo, hi}, t;\n\t"
        "abs.f32 lo, lo;\n\t"
        "abs.f32 hi, hi;\n\t"
        "mov.b64 t, {lo, hi};\n\t"
        "add.rn.f32x2 %0, %0, t;\n\t"
        "}"
        : "+l"(acc) : "l"(a), "l"(b));
}

__device__ __forceinline__ void stepN(unsigned long long& acc,
                                      unsigned long long a,
                                      unsigned long long b)
{
    asm("{\n\t"
        ".reg .b64 t;\n\t"
        ".reg .f32 lo, hi;\n\t"
        "add.rn.f32x2 t, %1, %2;\n\t"
        "mov.b64 {lo, hi}, t;\n\t"
        "abs.f32 lo, lo;\n\t"
        "abs.f32 hi, hi;\n\t"
        "neg.f32 lo, lo;\n\t"
        "neg.f32 hi, hi;\n\t"
        "mov.b64 t, {lo, hi};\n\t"
        "add.rn.f32x2 %0, %0, t;\n\t"
        "}"
        : "+l"(acc) : "l"(a), "l"(b));
}

__device__ __forceinline__ void stepM(unsigned long long& acc,
                                      unsigned long long a,
                                      unsigned long long b,
                                      unsigned long long sv)
{
    asm("{\n\t"
        ".reg .b64 t;\n\t"
        ".reg .f32 lo, hi;\n\t"
        "add.rn.f32x2 t, %1, %2;\n\t"
        "mov.b64 {lo, hi}, t;\n\t"
        "abs.f32 lo, lo;\n\t"
        "abs.f32 hi, hi;\n\t"
        "mov.b64 t, {lo, hi};\n\t"
        "fma.rn.f32x2 %0, t, %3, %0;\n\t"
        "}"
        : "+l"(acc) : "l"(a), "l"(b), "l"(sv));
}

// ---------------------------------------------------------------------------
// Main kernel: 128 threads, 64x64 tile, 8n x 4m per thread, 4 CTAs/SM.
// Segmented h2 loop: [0,K1) += |t| ; mixed (+,-) ; rest -= |t|.
// ---------------------------------------------------------------------------
__global__ void __launch_bounds__(128, 4) qmain_kernel(
    float* __restrict__ out, int N, int M)
{
    __shared__ unsigned long long sA[HP][64];   // 16 KB
    __shared__ unsigned long long sB[HP][64];   // 16 KB
    __shared__ float sP[64];
    __shared__ float sR[64];

    const int tid = threadIdx.x;
    const int nBase = blockIdx.y * 64;
    const int mBase = blockIdx.x * 64;

    const int K1  = g_K1;
    const int mix = g_mix;

    if (tid < 64) sP[tid] = g_P[nBase + tid];
    else          sR[tid - 64] = g_R[mBase + (tid - 64)];

    #pragma unroll
    for (int i = 0; i < 16; ++i) {
        int idx = tid + i * 128;
        int h2 = idx >> 6, l = idx & 63;
        sA[h2][l] = g_aT[h2][nBase + l];
        sB[h2][l] = g_bT[h2][mBase + l];
    }
    __syncthreads();

    const int tx = tid & 15;        // m: 16 cols x 4
    const int ty = tid >> 4;        // n: 8 rows x 8
    const int n0 = ty * 8;
    const int m0 = tx * 4;

    unsigned long long acc[8][4];
    #pragma unroll
    for (int i = 0; i < 8; ++i)
        #pragma unroll
        for (int j = 0; j < 4; ++j)
            acc[i][j] = 0ull;

    unsigned long long A[8], B[4];

    int h2 = 0;
    #pragma unroll 4
    for (; h2 < K1; ++h2) {
        #pragma unroll
        for (int i = 0; i < 4; ++i) {
            ulonglong2 a = *(const ulonglong2*)&sA[h2][n0 + 2 * i];
            A[2 * i] = a.x; A[2 * i + 1] = a.y;
        }
        #pragma unroll
        for (int j = 0; j < 2; ++j) {
            ulonglong2 b = *(const ulonglong2*)&sB[h2][m0 + 2 * j];
            B[2 * j] = b.x; B[2 * j + 1] = b.y;
        }
        #pragma unroll
        for (int i = 0; i < 8; ++i)
            #pragma unroll
            for (int j = 0; j < 4; ++j)
                stepP(acc[i][j], A[i], B[j]);
    }

    if (mix) {
        const unsigned long long sv = pack2(1.0f, -1.0f);
        #pragma unroll
        for (int i = 0; i < 4; ++i) {
            ulonglong2 a = *(const ulonglong2*)&sA[h2][n0 + 2 * i];
            A[2 * i] = a.x; A[2 * i + 1] = a.y;
        }
        #pragma unroll
        for (int j = 0; j < 2; ++j) {
            ulonglong2 b = *(const ulonglong2*)&sB[h2][m0 + 2 * j];
            B[2 * j] = b.x; B[2 * j + 1] = b.y;
        }
        #pragma unroll
        for (int i = 0; i < 8; ++i)
            #pragma unroll
            for (int j = 0; j < 4; ++j)
                stepM(acc[i][j], A[i], B[j], sv);
        ++h2;
    }

    #pragma unroll 4
    for (; h2 < HP; ++h2) {
        #pragma unroll
        for (int i = 0; i < 4; ++i) {
            ulonglong2 a = *(const ulonglong2*)&sA[h2][n0 + 2 * i];
            A[2 * i] = a.x; A[2 * i + 1] = a.y;
        }
        #pragma unroll
        for (int j = 0; j < 2; ++j) {
            ulonglong2 b = *(const ulonglong2*)&sB[h2][m0 + 2 * j];
            B[2 * j] = b.x; B[2 * j + 1] = b.y;
        }
        #pragma unroll
        for (int i = 0; i < 8; ++i)
            #pragma unroll
            for (int j = 0; j < 4; ++j)
                stepN(acc[i][j], A[i], B[j]);
    }

    // Epilogue: r = acc.lo + acc.hi + P[n] + R[m]
    #pragma unroll
    for (int i = 0; i < 8; ++i) {
        const float pn = sP[n0 + i];
        float r[4];
        #pragma unroll
        for (int j = 0; j < 4; ++j) {
            unsigned long long u = acc[i][j];
            r[j] = (__uint_as_float((unsigned)u) +
                    __uint_as_float((unsigned)(u >> 32))) + (pn + sR[m0 + j]);
        }
        float4 v = make_float4(r[0], r[1], r[2], r[3]);
        *(float4*)&out[(size_t)(nBase + n0 + i) * M + (mBase + m0)] = v;
    }
}

// ---------------------------------------------------------------------------
// Launch
// ---------------------------------------------------------------------------
extern "C" void kernel_launch(void* const* d_in, const int* in_sizes, int n_in,
                              void* d_out, int out_size)
{
    const float* job  = (const float*)d_in[0];
    const float* mac  = (const float*)d_in[1];
    const float* gvec = (const float*)d_in[2];
    const float* Wj   = (const float*)d_in[3];
    const float* bj   = (const float*)d_in[4];
    const float* Wm   = (const float*)d_in[5];
    const float* bm   = (const float*)d_in[6];
    const float* Wg   = (const float*)d_in[7];
    const float* bg   = (const float*)d_in[8];
    const float* W1   = (const float*)d_in[9];
    const float* b1   = (const float*)d_in[10];
    const float* W2   = (const float*)d_in[11];
    const float* b2   = (const float*)d_in[12];
    float* out = (float*)d_out;

    const int N = in_sizes[0];
    const int M = in_sizes[1];

    int rows = N + M;
    precompute_kernel<<<(rows + 7) / 8, 256>>>(
        job, mac, gvec, Wj, bj, Wm, bm, Wg, bg, W1, b1, W2, b2, N, M);

    dim3 grid(M / 64, N / 64);
    qmain_kernel<<<grid, 128>>>(out, N, M);
}

// round 12
// speedup vs baseline: 1.2002x; 1.0609x over previous
#include <cuda_runtime.h>
#include <cstdint>

// ---------------------------------------------------------------------------
// Q[n,m] = P[n] + R[m] + sum_h (w2[h]/2)|a[n,h] + b[m,h]|
// Rows pre-scaled by |w|/2:  (w/2)|a+b| = sign(w) * |a' + b'|.
// h-space sign-partitioned: positives (rank 0..pc-1) then negatives.
// Precompute: features in ORIGINAL h order (coalesced W1 loads), permutation
// applied via popc-rank + per-warp smem scatter (no __fns, no gather shfl).
// qmain inner loop: add2 + add2 with |.|/-|.| folded as operand modifiers;
// warps de-phased via a MUFU rcp chain to break LDS-burst lockstep.
// ---------------------------------------------------------------------------

#define NMAX 2048
#define HID  64
#define HP   32   // h pairs

__device__ unsigned long long g_aT[HP][NMAX];  // scaled, permuted job rows
__device__ unsigned long long g_bT[HP][NMAX];  // scaled, permuted machine rows
__device__ float g_P[NMAX];
__device__ float g_R[NMAX];
__device__ int g_K1;           // # pure-positive pairs
__device__ int g_mix;          // 1 if a mixed (+,-) pair exists at slot K1

__device__ __forceinline__ unsigned long long pack2(float lo, float hi) {
    return (unsigned long long)__float_as_uint(lo) |
           ((unsigned long long)__float_as_uint(hi) << 32);
}

// rank of original index h within the sign partition (positives first).
__device__ __forceinline__ int rank_of(int h, unsigned bal0, unsigned bal1,
                                       int pc) {
    bool pos = (h < 32) ? ((bal0 >> h) & 1) : ((bal1 >> (h - 32)) & 1);
    unsigned b0 = pos ? bal0 : ~bal0;
    unsigned b1 = pos ? bal1 : ~bal1;
    int r = (h < 32) ? __popc(b0 & ((1u << h) - 1u))
                     : __popc(b0) + __popc(b1 & ((1u << (h - 32)) - 1u));
    return (pos ? 0 : pc) + r;
}

// ---------------------------------------------------------------------------
// Precompute: one warp per row; lane = h-pair (original order).
// Scatter scaled values through per-warp smem staging to apply permutation.
// ---------------------------------------------------------------------------
__global__ void __launch_bounds__(256) precompute_kernel(
    const float* __restrict__ job, const float* __restrict__ mac,
    const float* __restrict__ gvec,
    const float* __restrict__ Wj, const float* __restrict__ bj,
    const float* __restrict__ Wm, const float* __restrict__ bm,
    const float* __restrict__ Wg, const float* __restrict__ bg,
    const float* __restrict__ W1, const float* __restrict__ b1,
    const float* __restrict__ W2, const float* __restrict__ b2,
    int n, int m)
{
    __shared__ __align__(8) float stage[8][64];

    const int wrp  = threadIdx.x >> 5;
    const int row  = blockIdx.x * 8 + wrp;
    const int lane = threadIdx.x & 31;
    if (row >= n + m) return;   // row is warp-uniform: whole warp exits

    // Sign partition (identical in every warp, deterministic).
    const float w_lo = W2[lane];
    const float w_hi = W2[lane + 32];
    const unsigned bal0 = __ballot_sync(0xFFFFFFFFu, w_lo >= 0.0f);
    const unsigned bal1 = __ballot_sync(0xFFFFFFFFu, w_hi >= 0.0f);
    const int pc = __popc(bal0) + __popc(bal1);

    if (blockIdx.x == 0 && threadIdx.x == 0) {
        g_K1  = pc >> 1;
        g_mix = pc & 1;
    }

    const float2 w2p = *(const float2*)&W2[2 * lane];  // own original pair

    float f0, f1;   // features for ORIGINAL h = 2*lane, 2*lane+1
    if (row < n) {
        const float x = job[row];
        f0 = 0.0f; f1 = 0.0f;
        #pragma unroll
        for (int j = 0; j < 16; ++j) {
            float f = fmaxf(fmaf(x, Wj[j], bj[j]), 0.0f);
            float2 w = *(const float2*)&W1[j * HID + 2 * lane];
            f0 = fmaf(f, w.x, f0);
            f1 = fmaf(f, w.y, f1);
        }
    } else {
        const int mm = row - n;
        const float x = mac[mm];
        float2 bb = *(const float2*)&b1[2 * lane];
        f0 = bb.x; f1 = bb.y;
        #pragma unroll
        for (int k = 0; k < 8; ++k) {
            float gf = bg[k];
            #pragma unroll
            for (int i = 0; i < 8; ++i)
                gf = fmaf(gvec[i], Wg[i * 8 + k], gf);
            gf = fmaxf(gf, 0.0f);
            float2 w = *(const float2*)&W1[(32 + k) * HID + 2 * lane];
            f0 = fmaf(gf, w.x, f0);
            f1 = fmaf(gf, w.y, f1);
        }
        #pragma unroll
        for (int j = 0; j < 16; ++j) {
            float f = fmaxf(fmaf(x, Wm[j], bm[j]), 0.0f);
            float2 w = *(const float2*)&W1[(16 + j) * HID + 2 * lane];
            f0 = fmaf(f, w.x, f0);
            f1 = fmaf(f, w.y, f1);
        }
    }

    // Rank-1 term (permutation-invariant, original order).
    float s = f0 * (0.5f * w2p.x) + f1 * (0.5f * w2p.y);
    #pragma unroll
    for (int d = 16; d > 0; d >>= 1)
        s += __shfl_xor_sync(0xFFFFFFFFu, s, d);

    // Scatter scaled values to permuted slots via smem staging.
    const int r0 = rank_of(2 * lane,     bal0, bal1, pc);
    const int r1 = rank_of(2 * lane + 1, bal0, bal1, pc);
    stage[wrp][r0] = f0 * (0.5f * fabsf(w2p.x));
    stage[wrp][r1] = f1 * (0.5f * fabsf(w2p.y));
    __syncwarp();
    const float2 v = *(const float2*)&stage[wrp][2 * lane];
    const unsigned long long packed = pack2(v.x, v.y);

    if (row < n) {
        g_aT[lane][row] = packed;
        if (lane == 0) g_P[row] = s + b2[0];
    } else {
        g_bT[lane][row - n] = packed;
        if (lane == 0) g_R[row - n] = s;
    }
}

// ---------------------------------------------------------------------------
// Steps. abs/neg fold into the FADD2 source operand modifier.
// ---------------------------------------------------------------------------
__device__ __forceinline__ void stepP(unsigned long long& acc,
                                      unsigned long long a,
                                      unsigned long long b)
{
    asm("{\n\t"
        ".reg .b64 t;\n\t"
        ".reg .f32 lo, hi;\n\t"
        "add.rn.f32x2 t, %1, %2;\n\t"
        "mov.b64 {lo, hi}, t;\n\t"
        "abs.f32 lo, lo;\n\t"
        "abs.f32 hi, hi;\n\t"
        "mov.b64 t, {lo, hi};\n\t"
        "add.rn.f32x2 %0, %0, t;\n\t"
        "}"
        : "+l"(acc) : "l"(a), "l"(b));
}

__device__ __forceinline__ void stepN(unsigned long long& acc,
                                      unsigned long long a,
                                      unsigned long long b)
{
    asm("{\n\t"
        ".reg .b64 t;\n\t"
        ".reg .f32 lo, hi;\n\t"
        "add.rn.f32x2 t, %1, %2;\n\t"
        "mov.b64 {lo, hi}, t;\n\t"
        "abs.f32 lo, lo;\n\t"
        "abs.f32 hi, hi;\n\t"
        "neg.f32 lo, lo;\n\t"
        "neg.f32 hi, hi;\n\t"
        "mov.b64 t, {lo, hi};\n\t"
        "add.rn.f32x2 %0, %0, t;\n\t"
        "}"
        : "+l"(acc) : "l"(a), "l"(b));
}

__device__ __forceinline__ void stepM(unsigned long long& acc,
                                      unsigned long long a,
                                      unsigned long long b,
                                      unsigned long long sv)
{
    asm("{\n\t"
        ".reg .b64 t;\n\t"
        ".reg .f32 lo, hi;\n\t"
        "add.rn.f32x2 t, %1, %2;\n\t"
        "mov.b64 {lo, hi}, t;\n\t"
        "abs.f32 lo, lo;\n\t"
        "abs.f32 hi, hi;\n\t"
        "mov.b64 t, {lo, hi};\n\t"
        "fma.rn.f32x2 %0, t, %3, %0;\n\t"
        "}"
        : "+l"(acc) : "l"(a), "l"(b), "l"(sv));
}

// ---------------------------------------------------------------------------
// Main kernel: 128 threads, 64x64 tile, 8n x 4m per thread, 4 CTAs/SM.
// Segmented h2 loop: [0,K1) += |t| ; mixed (+,-) ; rest -= |t|.
// Warps de-phased post-sync via a dependent MUFU rcp chain.
// ---------------------------------------------------------------------------
__global__ void __launch_bounds__(128, 4) qmain_kernel(
    float* __restrict__ out, int N, int M)
{
    __shared__ unsigned long long sA[HP][64];   // 16 KB
    __shared__ unsigned long long sB[HP][64];   // 16 KB
    __shared__ float sP[64];
    __shared__ float sR[64];

    const int tid = threadIdx.x;
    const int nBase = blockIdx.y * 64;
    const int mBase = blockIdx.x * 64;

    const int K1  = g_K1;
    const int mix = g_mix;

    if (tid < 64) sP[tid] = g_P[nBase + tid];
    else          sR[tid - 64] = g_R[mBase + (tid - 64)];

    #pragma unroll
    for (int i = 0; i < 16; ++i) {
        int idx = tid + i * 128;
        int h2 = idx >> 6, l = idx & 63;
        sA[h2][l] = g_aT[h2][nBase + l];
        sB[h2][l] = g_bT[h2][mBase + l];
    }
    __syncthreads();

    // De-phase warps on the SM: slot 0..15 -> 0..240 cyc dependent MUFU chain.
    {
        int slot = (((blockIdx.x + blockIdx.y) & 3) << 2) | (tid >> 5);
        float d = (float)(tid + 3);
        for (int k = 0; k < slot; ++k)
            asm volatile("rcp.approx.f32 %0, %0;" : "+f"(d));
        asm volatile("" :: "f"(d));   // keep the chain alive, emits nothing
    }

    const int tx = tid & 15;        // m: 16 cols x 4
    const int ty = tid >> 4;        // n: 8 rows x 8
    const int n0 = ty * 8;
    const int m0 = tx * 4;

    unsigned long long acc[8][4];
    #pragma unroll
    for (int i = 0; i < 8; ++i)
        #pragma unroll
        for (int j = 0; j < 4; ++j)
            acc[i][j] = 0ull;

    unsigned long long A[8], B[4];

    int h2 = 0;
    #pragma unroll 4
    for (; h2 < K1; ++h2) {
        #pragma unroll
        for (int i = 0; i < 4; ++i) {
            ulonglong2 a = *(const ulonglong2*)&sA[h2][n0 + 2 * i];
            A[2 * i] = a.x; A[2 * i + 1] = a.y;
        }
        #pragma unroll
        for (int j = 0; j < 2; ++j) {
            ulonglong2 b = *(const ulonglong2*)&sB[h2][m0 + 2 * j];
            B[2 * j] = b.x; B[2 * j + 1] = b.y;
        }
        #pragma unroll
        for (int i = 0; i < 8; ++i)
            #pragma unroll
            for (int j = 0; j < 4; ++j)
                stepP(acc[i][j], A[i], B[j]);
    }

    if (mix) {
        const unsigned long long sv = pack2(1.0f, -1.0f);
        #pragma unroll
        for (int i = 0; i < 4; ++i) {
            ulonglong2 a = *(const ulonglong2*)&sA[h2][n0 + 2 * i];
            A[2 * i] = a.x; A[2 * i + 1] = a.y;
        }
        #pragma unroll
        for (int j = 0; j < 2; ++j) {
            ulonglong2 b = *(const ulonglong2*)&sB[h2][m0 + 2 * j];
            B[2 * j] = b.x; B[2 * j + 1] = b.y;
        }
        #pragma unroll
        for (int i = 0; i < 8; ++i)
            #pragma unroll
            for (int j = 0; j < 4; ++j)
                stepM(acc[i][j], A[i], B[j], sv);
        ++h2;
    }

    #pragma unroll 4
    for (; h2 < HP; ++h2) {
        #pragma unroll
        for (int i = 0; i < 4; ++i) {
            ulonglong2 a = *(const ulonglong2*)&sA[h2][n0 + 2 * i];
            A[2 * i] = a.x; A[2 * i + 1] = a.y;
        }
        #pragma unroll
        for (int j = 0; j < 2; ++j) {
            ulonglong2 b = *(const ulonglong2*)&sB[h2][m0 + 2 * j];
            B[2 * j] = b.x; B[2 * j + 1] = b.y;
        }
        #pragma unroll
        for (int i = 0; i < 8; ++i)
            #pragma unroll
            for (int j = 0; j < 4; ++j)
                stepN(acc[i][j], A[i], B[j]);
    }

    // Epilogue: r = acc.lo + acc.hi + P[n] + R[m]
    #pragma unroll
    for (int i = 0; i < 8; ++i) {
        const float pn = sP[n0 + i];
        float r[4];
        #pragma unroll
        for (int j = 0; j < 4; ++j) {
            unsigned long long u = acc[i][j];
            r[j] = (__uint_as_float((unsigned)u) +
                    __uint_as_float((unsigned)(u >> 32))) + (pn + sR[m0 + j]);
        }
        float4 v = make_float4(r[0], r[1], r[2], r[3]);
        *(float4*)&out[(size_t)(nBase + n0 + i) * M + (mBase + m0)] = v;
    }
}

// ---------------------------------------------------------------------------
// Launch
// ---------------------------------------------------------------------------
extern "C" void kernel_launch(void* const* d_in, const int* in_sizes, int n_in,
                              void* d_out, int out_size)
{
    const float* job  = (const float*)d_in[0];
    const float* mac  = (const float*)d_in[1];
    const float* gvec = (const float*)d_in[2];
    const float* Wj   = (const float*)d_in[3];
    const float* bj   = (const float*)d_in[4];
    const float* Wm   = (const float*)d_in[5];
    const float* bm   = (const float*)d_in[6];
    const float* Wg   = (const float*)d_in[7];
    const float* bg   = (const float*)d_in[8];
    const float* W1   = (const float*)d_in[9];
    const float* b1   = (const float*)d_in[10];
    const float* W2   = (const float*)d_in[11];
    const float* b2   = (const float*)d_in[12];
    float* out = (float*)d_out;

    const int N = in_sizes[0];
    const int M = in_sizes[1];

    int rows = N + M;
    precompute_kernel<<<(rows + 7) / 8, 256>>>(
        job, mac, gvec, Wj, bj, Wm, bm, Wg, bg, W1, b1, W2, b2, N, M);

    dim3 grid(M / 64, N / 64);
    qmain_kernel<<<grid, 128>>>(out, N, M);
}

// round 13
// speedup vs baseline: 1.2094x; 1.0077x over previous
#include <cuda_runtime.h>
#include <cstdint>

// ---------------------------------------------------------------------------
// Q[n,m] = P[n] + R[m] + sum_h (w2[h]/2)|a[n,h] + b[m,h]|
// Rows pre-scaled by |w|/2:  (w/2)|a+b| = sign(w) * |a' + b'|.
// h-space sign-partitioned: positives (rank 0..pc-1) then negatives.
// Precompute: features in ORIGINAL h order (coalesced W1 loads), permutation
// applied via popc-rank + per-warp smem scatter.
// qmain inner loop: add2 + add2 with |.|/-|.| folded as operand modifiers.
// ---------------------------------------------------------------------------

#define NMAX 2048
#define HID  64
#define HP   32   // h pairs

__device__ unsigned long long g_aT[HP][NMAX];  // scaled, permuted job rows
__device__ unsigned long long g_bT[HP][NMAX];  // scaled, permuted machine rows
__device__ float g_P[NMAX];
__device__ float g_R[NMAX];
__device__ int g_K1;           // # pure-positive pairs
__device__ int g_mix;          // 1 if a mixed (+,-) pair exists at slot K1

__device__ __forceinline__ unsigned long long pack2(float lo, float hi) {
    return (unsigned long long)__float_as_uint(lo) |
           ((unsigned long long)__float_as_uint(hi) << 32);
}

// rank of original index h within the sign partition (positives first).
__device__ __forceinline__ int rank_of(int h, unsigned bal0, unsigned bal1,
                                       int pc) {
    bool pos = (h < 32) ? ((bal0 >> h) & 1) : ((bal1 >> (h - 32)) & 1);
    unsigned b0 = pos ? bal0 : ~bal0;
    unsigned b1 = pos ? bal1 : ~bal1;
    int r = (h < 32) ? __popc(b0 & ((1u << h) - 1u))
                     : __popc(b0) + __popc(b1 & ((1u << (h - 32)) - 1u));
    return (pos ? 0 : pc) + r;
}

// ---------------------------------------------------------------------------
// Precompute: one warp per row; lane = h-pair (original order).
// Scatter scaled values through per-warp smem staging to apply permutation.
// ---------------------------------------------------------------------------
__global__ void __launch_bounds__(256) precompute_kernel(
    const float* __restrict__ job, const float* __restrict__ mac,
    const float* __restrict__ gvec,
    const float* __restrict__ Wj, const float* __restrict__ bj,
    const float* __restrict__ Wm, const float* __restrict__ bm,
    const float* __restrict__ Wg, const float* __restrict__ bg,
    const float* __restrict__ W1, const float* __restrict__ b1,
    const float* __restrict__ W2, const float* __restrict__ b2,
    int n, int m)
{
    __shared__ __align__(8) float stage[8][64];

    const int wrp  = threadIdx.x >> 5;
    const int row  = blockIdx.x * 8 + wrp;
    const int lane = threadIdx.x & 31;
    if (row >= n + m) return;   // row is warp-uniform: whole warp exits

    // Sign partition (identical in every warp, deterministic).
    const float w_lo = W2[lane];
    const float w_hi = W2[lane + 32];
    const unsigned bal0 = __ballot_sync(0xFFFFFFFFu, w_lo >= 0.0f);
    const unsigned bal1 = __ballot_sync(0xFFFFFFFFu, w_hi >= 0.0f);
    const int pc = __popc(bal0) + __popc(bal1);

    if (blockIdx.x == 0 && threadIdx.x == 0) {
        g_K1  = pc >> 1;
        g_mix = pc & 1;
    }

    const float2 w2p = *(const float2*)&W2[2 * lane];  // own original pair

    float f0, f1;   // features for ORIGINAL h = 2*lane, 2*lane+1
    if (row < n) {
        const float x = job[row];
        f0 = 0.0f; f1 = 0.0f;
        #pragma unroll
        for (int j = 0; j < 16; ++j) {
            float f = fmaxf(fmaf(x, Wj[j], bj[j]), 0.0f);
            float2 w = *(const float2*)&W1[j * HID + 2 * lane];
            f0 = fmaf(f, w.x, f0);
            f1 = fmaf(f, w.y, f1);
        }
    } else {
        const int mm = row - n;
        const float x = mac[mm];
        float2 bb = *(const float2*)&b1[2 * lane];
        f0 = bb.x; f1 = bb.y;
        #pragma unroll
        for (int k = 0; k < 8; ++k) {
            float gf = bg[k];
            #pragma unroll
            for (int i = 0; i < 8; ++i)
                gf = fmaf(gvec[i], Wg[i * 8 + k], gf);
            gf = fmaxf(gf, 0.0f);
            float2 w = *(const float2*)&W1[(32 + k) * HID + 2 * lane];
            f0 = fmaf(gf, w.x, f0);
            f1 = fmaf(gf, w.y, f1);
        }
        #pragma unroll
        for (int j = 0; j < 16; ++j) {
            float f = fmaxf(fmaf(x, Wm[j], bm[j]), 0.0f);
            float2 w = *(const float2*)&W1[(16 + j) * HID + 2 * lane];
            f0 = fmaf(f, w.x, f0);
            f1 = fmaf(f, w.y, f1);
        }
    }

    // Rank-1 term (permutation-invariant, original order).
    float s = f0 * (0.5f * w2p.x) + f1 * (0.5f * w2p.y);
    #pragma unroll
    for (int d = 16; d > 0; d >>= 1)
        s += __shfl_xor_sync(0xFFFFFFFFu, s, d);

    // Scatter scaled values to permuted slots via smem staging.
    const int r0 = rank_of(2 * lane,     bal0, bal1, pc);
    const int r1 = rank_of(2 * lane + 1, bal0, bal1, pc);
    stage[wrp][r0] = f0 * (0.5f * fabsf(w2p.x));
    stage[wrp][r1] = f1 * (0.5f * fabsf(w2p.y));
    __syncwarp();
    const float2 v = *(const float2*)&stage[wrp][2 * lane];
    const unsigned long long packed = pack2(v.x, v.y);

    if (row < n) {
        g_aT[lane][row] = packed;
        if (lane == 0) g_P[row] = s + b2[0];
    } else {
        g_bT[lane][row - n] = packed;
        if (lane == 0) g_R[row - n] = s;
    }
}

// ---------------------------------------------------------------------------
// Steps. abs/neg fold into the FADD2 source operand modifier.
// ---------------------------------------------------------------------------
__device__ __forceinline__ void stepP(unsigned long long& acc,
                                      unsigned long long a,
                                      unsigned long long b)
{
    asm("{\n\t"
        ".reg .b64 t;\n\t"
        ".reg .f32 lo, hi;\n\t"
        "add.rn.f32x2 t, %1, %2;\n\t"
        "mov.b64 {lo, hi}, t;\n\t"
        "abs.f32 lo, lo;\n\t"
        "abs.f32 hi, hi;\n\t"
        "mov.b64 t, {lo, hi};\n\t"
        "add.rn.f32x2 %0, %0, t;\n\t"
        "}"
        : "+l"(acc) : "l"(a), "l"(b));
}

__device__ __forceinline__ void stepN(unsigned long long& acc,
                                      unsigned long long a,
                                      unsigned long long b)
{
    asm("{\n\t"
        ".reg .b64 t;\n\t"
        ".reg .f32 lo, hi;\n\t"
        "add.rn.f32x2 t, %1, %2;\n\t"
        "mov.b64 {lo, hi}, t;\n\t"
        "abs.f32 lo, lo;\n\t"
        "abs.f32 hi, hi;\n\t"
        "neg.f32 lo, lo;\n\t"
        "neg.f32 hi, hi;\n\t"
        "mov.b64 t, {lo, hi};\n\t"
        "add.rn.f32x2 %0, %0, t;\n\t"
        "}"
        : "+l"(acc) : "l"(a), "l"(b));
}

__device__ __forceinline__ void stepM(unsigned long long& acc,
                                      unsigned long long a,
                                      unsigned long long b,
                                      unsigned long long sv)
{
    asm("{\n\t"
        ".reg .b64 t;\n\t"
        ".reg .f32 lo, hi;\n\t"
        "add.rn.f32x2 t, %1, %2;\n\t"
        "mov.b64 {lo, hi}, t;\n\t"
        "abs.f32 lo, lo;\n\t"
        "abs.f32 hi, hi;\n\t"
        "mov.b64 t, {lo, hi};\n\t"
        "fma.rn.f32x2 %0, t, %3, %0;\n\t"
        "}"
        : "+l"(acc) : "l"(a), "l"(b), "l"(sv));
}

// ---------------------------------------------------------------------------
// Main kernel: 128 threads, 64x64 tile, 8n x 4m per thread, 4 CTAs/SM.
// Segmented h2 loop: [0,K1) += |t| ; mixed (+,-) ; rest -= |t|.
// ---------------------------------------------------------------------------
__global__ void __launch_bounds__(128, 4) qmain_kernel(
    float* __restrict__ out, int N, int M)
{
    __shared__ unsigned long long sA[HP][64];   // 16 KB
    __shared__ unsigned long long sB[HP][64];   // 16 KB
    __shared__ float sP[64];
    __shared__ float sR[64];

    const int tid = threadIdx.x;
    const int nBase = blockIdx.y * 64;
    const int mBase = blockIdx.x * 64;

    const int K1  = g_K1;
    const int mix = g_mix;

    if (tid < 64) sP[tid] = g_P[nBase + tid];
    else          sR[tid - 64] = g_R[mBase + (tid - 64)];

    #pragma unroll
    for (int i = 0; i < 16; ++i) {
        int idx = tid + i * 128;
        int h2 = idx >> 6, l = idx & 63;
        sA[h2][l] = g_aT[h2][nBase + l];
        sB[h2][l] = g_bT[h2][mBase + l];
    }
    __syncthreads();

    const int tx = tid & 15;        // m: 16 cols x 4
    const int ty = tid >> 4;        // n: 8 rows x 8
    const int n0 = ty * 8;
    const int m0 = tx * 4;

    unsigned long long acc[8][4];
    #pragma unroll
    for (int i = 0; i < 8; ++i)
        #pragma unroll
        for (int j = 0; j < 4; ++j)
            acc[i][j] = 0ull;

    unsigned long long A[8], B[4];

    int h2 = 0;
    #pragma unroll 4
    for (; h2 < K1; ++h2) {
        #pragma unroll
        for (int i = 0; i < 4; ++i) {
            ulonglong2 a = *(const ulonglong2*)&sA[h2][n0 + 2 * i];
            A[2 * i] = a.x; A[2 * i + 1] = a.y;
        }
        #pragma unroll
        for (int j = 0; j < 2; ++j) {
            ulonglong2 b = *(const ulonglong2*)&sB[h2][m0 + 2 * j];
            B[2 * j] = b.x; B[2 * j + 1] = b.y;
        }
        #pragma unroll
        for (int i = 0; i < 8; ++i)
            #pragma unroll
            for (int j = 0; j < 4; ++j)
                stepP(acc[i][j], A[i], B[j]);
    }

    if (mix) {
        const unsigned long long sv = pack2(1.0f, -1.0f);
        #pragma unroll
        for (int i = 0; i < 4; ++i) {
            ulonglong2 a = *(const ulonglong2*)&sA[h2][n0 + 2 * i];
            A[2 * i] = a.x; A[2 * i + 1] = a.y;
        }
        #pragma unroll
        for (int j = 0; j < 2; ++j) {
            ulonglong2 b = *(const ulonglong2*)&sB[h2][m0 + 2 * j];
            B[2 * j] = b.x; B[2 * j + 1] = b.y;
        }
        #pragma unroll
        for (int i = 0; i < 8; ++i)
            #pragma unroll
            for (int j = 0; j < 4; ++j)
                stepM(acc[i][j], A[i], B[j], sv);
        ++h2;
    }

    #pragma unroll 4
    for (; h2 < HP; ++h2) {
        #pragma unroll
        for (int i = 0; i < 4; ++i) {
            ulonglong2 a = *(const ulonglong2*)&sA[h2][n0 + 2 * i];
            A[2 * i] = a.x; A[2 * i + 1] = a.y;
        }
        #pragma unroll
        for (int j = 0; j < 2; ++j) {
            ulonglong2 b = *(const ulonglong2*)&sB[h2][m0 + 2 * j];
            B[2 * j] = b.x; B[2 * j + 1] = b.y;
        }
        #pragma unroll
        for (int i = 0; i < 8; ++i)
            #pragma unroll
            for (int j = 0; j < 4; ++j)
                stepN(acc[i][j], A[i], B[j]);
    }

    // Epilogue: r = acc.lo + acc.hi + P[n] + R[m]
    #pragma unroll
    for (int i = 0; i < 8; ++i) {
        const float pn = sP[n0 + i];
        float r[4];
        #pragma unroll
        for (int j = 0; j < 4; ++j) {
            unsigned long long u = acc[i][j];
            r[j] = (__uint_as_float((unsigned)u) +
                    __uint_as_float((unsigned)(u >> 32))) + (pn + sR[m0 + j]);
        }
        float4 v = make_float4(r[0], r[1], r[2], r[3]);
        *(float4*)&out[(size_t)(nBase + n0 + i) * M + (mBase + m0)] = v;
    }
}

// ---------------------------------------------------------------------------
// Launch
// ---------------------------------------------------------------------------
extern "C" void kernel_launch(void* const* d_in, const int* in_sizes, int n_in,
                              void* d_out, int out_size)
{
    const float* job  = (const float*)d_in[0];
    const float* mac  = (const float*)d_in[1];
    const float* gvec = (const float*)d_in[2];
    const float* Wj   = (const float*)d_in[3];
    const float* bj   = (const float*)d_in[4];
    const float* Wm   = (const float*)d_in[5];
    const float* bm   = (const float*)d_in[6];
    const float* Wg   = (const float*)d_in[7];
    const float* bg   = (const float*)d_in[8];
    const float* W1   = (const float*)d_in[9];
    const float* b1   = (const float*)d_in[10];
    const float* W2   = (const float*)d_in[11];
    const float* b2   = (const float*)d_in[12];
    float* out = (float*)d_out;

    const int N = in_sizes[0];
    const int M = in_sizes[1];

    int rows = N + M;
    precompute_kernel<<<(rows + 7) / 8, 256>>>(
        job, mac, gvec, Wj, bj, Wm, bm, Wg, bg, W1, b1, W2, b2, N, M);

    dim3 grid(M / 64, N / 64);
    qmain_kernel<<<grid, 128>>>(out, N, M);
}